// round 15
// baseline (speedup 1.0000x reference)
#include <cuda_runtime.h>
#include <cuda_bf16.h>
#include <cstdint>

#define NNODES 100000
#define D      128
#define S      16
#define NBATCH 8192
#define NT1    768
#define NP1    512                   // 16 producer warps, 8 consumer warps
#define NBLK1  152
#define GT_ALL (NBLK1 * NT1)

#define TILE1  32
#define KSTR   264                   // bf16 row stride (256 + 8 pad)

// ---- layer-1 smem offsets ----
#define L1_BHI   0
#define L1_BLO   67584
#define L1_A0    135168
#define L1_ABUF  33792
#define L1_AHALF 16896
#define L1_BIAS  202752
#define SMEM1_SZ 203264

// ---- layer-2 smem offsets (32-node tile, 2 blocks/SM) ----
#define L2_BHI   0
#define L2_BLO   33792
#define L2_AHI   67584
#define L2_ALO   84480
#define L2_BIAS  101376
#define SMEM2_SZ 101632
#define NT2      512
#define TILE2    32

__device__ float g_h1[(size_t)NNODES * D];
__device__ float g_W2p[256 * 64];
__device__ float g_b2p[64];
__device__ unsigned char g_mark[NNODES];
__device__ int  g_list[NNODES];
__device__ int  g_ctrs[2];           // [0]=frontier count, [1]=grid barrier

// ---------------- helpers ----------------
__device__ __forceinline__ uint32_t pbf2(float lo, float hi) {
    uint32_t r;
    asm("cvt.rn.bf16x2.f32 %0, %1, %2;" : "=r"(r) : "f"(hi), "f"(lo));
    return r;
}
__device__ __forceinline__ float bfr(float f) {
    return __bfloat162float(__float2bfloat16_rn(f));
}
__device__ __forceinline__ uint32_t lds32(uint32_t a) {
    uint32_t v; asm volatile("ld.shared.b32 %0, [%1];" : "=r"(v) : "r"(a)); return v;
}
__device__ __forceinline__ uint32_t smem_u32(const void* p) {
    uint32_t a;
    asm("{ .reg .u64 t; cvta.to.shared.u64 t, %1; cvt.u32.u64 %0, t; }"
        : "=r"(a) : "l"(p));
    return a;
}
__device__ __forceinline__ void mma_bf16(float c[4], uint32_t a0, uint32_t a1,
                                         uint32_t a2, uint32_t a3,
                                         uint32_t b0, uint32_t b1) {
    asm volatile(
        "mma.sync.aligned.m16n8k16.row.col.f32.bf16.bf16.f32 "
        "{%0,%1,%2,%3}, {%4,%5,%6,%7}, {%8,%9}, {%0,%1,%2,%3};"
        : "+f"(c[0]), "+f"(c[1]), "+f"(c[2]), "+f"(c[3])
        : "r"(a0), "r"(a1), "r"(a2), "r"(a3), "r"(b0), "r"(b1));
}

#define BAR_SYNC(id, n)   asm volatile("bar.sync %0, %1;"   :: "r"(id), "r"(n) : "memory")
#define BAR_ARRIVE(id, n) asm volatile("bar.arrive %0, %1;" :: "r"(id), "r"(n) : "memory")

// Software grid barrier: all NBLK1 blocks are co-resident (1 block/SM by smem).
__device__ __forceinline__ void grid_bar(int target) {
    __syncthreads();
    if (threadIdx.x == 0) {
        __threadfence();
        atomicAdd(&g_ctrs[1], 1);
        while (atomicAdd(&g_ctrs[1], 0) < target) { }
    }
    __syncthreads();
    __threadfence();
}

// float4-granularity gather+split (R10-proven)
__device__ __forceinline__ void gather_split(
    const float* __restrict__ src, const int* nb, int node, int nn, int d4,
    char* Ahi, char* Alo)
{
    const float4 self = *((const float4*)(src + (size_t)node * D) + d4);
    float4 m = *((const float4*)(src + (size_t)nb[0] * D) + d4);
    #pragma unroll
    for (int s = 1; s < S; s++) {
        float4 v = *((const float4*)(src + (size_t)nb[s] * D) + d4);
        m.x = fmaxf(m.x, v.x); m.y = fmaxf(m.y, v.y);
        m.z = fmaxf(m.z, v.z); m.w = fmaxf(m.w, v.w);
    }
    const int ks = d4 * 4;
    const int ka = D + ks;
    uint2 v;
    v.x = pbf2(self.x, self.y); v.y = pbf2(self.z, self.w);
    *(uint2*)(Ahi + (nn * KSTR + ks) * 2) = v;
    v.x = pbf2(self.x - bfr(self.x), self.y - bfr(self.y));
    v.y = pbf2(self.z - bfr(self.z), self.w - bfr(self.w));
    *(uint2*)(Alo + (nn * KSTR + ks) * 2) = v;
    v.x = pbf2(m.x, m.y); v.y = pbf2(m.z, m.w);
    *(uint2*)(Ahi + (nn * KSTR + ka) * 2) = v;
    v.x = pbf2(m.x - bfr(m.x), m.y - bfr(m.y));
    v.y = pbf2(m.z - bfr(m.z), m.w - bfr(m.w));
    *(uint2*)(Alo + (nn * KSTR + ka) * 2) = v;
}

// ---------------------------------------------------------------------------
// Layer 1 FUSED: [zero marks | W2p/b2p prep | W1 staging] -> bar ->
//                mark -> bar -> compact -> bar -> R10 producer/consumer loop
// ---------------------------------------------------------------------------
extern "C" __global__ void __launch_bounds__(NT1, 1)
sage_layer1(const float* __restrict__ x, const int* __restrict__ nidx,
            const int* __restrict__ batch,
            const float* __restrict__ W1, const float* __restrict__ b1,
            const float* __restrict__ W2, const float* __restrict__ b2,
            const float* __restrict__ Wout, const float* __restrict__ bout)
{
    extern __shared__ char smem[];
    const uint32_t sb = smem_u32(smem);
    float* biass = (float*)(smem + L1_BIAS);

    const int tid = threadIdx.x;
    const int gt  = blockIdx.x * NT1 + tid;

    // ---- phase 0a: zero mark array (100000 B = 25000 ints; GT_ALL > 25000) ----
    if (gt < NNODES / 4) ((int*)g_mark)[gt] = 0;

    // ---- phase 0b: W2p = W2 @ Wout, b2p = b2 @ Wout + bout ----
    if (gt < 256 * 64) {
        const int k = gt >> 6, n = gt & 63;
        const float* w2r = W2 + k * 128;
        float s0 = 0.f, s1 = 0.f, s2 = 0.f, s3 = 0.f;
        #pragma unroll 8
        for (int j = 0; j < 128; j += 4) {
            s0 += w2r[j + 0] * Wout[(j + 0) * 64 + n];
            s1 += w2r[j + 1] * Wout[(j + 1) * 64 + n];
            s2 += w2r[j + 2] * Wout[(j + 2) * 64 + n];
            s3 += w2r[j + 3] * Wout[(j + 3) * 64 + n];
        }
        g_W2p[gt] = (s0 + s1) + (s2 + s3);
    }
    if (gt >= 256 * 64 && gt < 256 * 64 + 64) {
        const int n = gt - 256 * 64;
        float t = bout[n];
        #pragma unroll 8
        for (int j = 0; j < 128; j++) t += b2[j] * Wout[j * 64 + n];
        g_b2p[n] = t;
    }

    // ---- phase 0c: stage W1 split+transposed into smem ----
    if (tid < 128) biass[tid] = b1[tid];
    for (int i = tid; i < 256 * 128; i += NT1) {
        const int k = i >> 7, n = i & 127;
        const float w = W1[(size_t)k * 128 + n];
        const float h = bfr(w);
        *(__nv_bfloat16*)(smem + L1_BHI + (n * KSTR + k) * 2) = __float2bfloat16_rn(w);
        *(__nv_bfloat16*)(smem + L1_BLO + (n * KSTR + k) * 2) = __float2bfloat16_rn(w - h);
    }

    grid_bar(NBLK1);          // marks zeroed everywhere

    // ---- phase 1: mark frontier (GT_ALL > NBATCH -> single pass) ----
    if (gt < NBATCH) {
        const int b = __ldg(batch + gt);
        g_mark[b] = 1;
        const int4* np = (const int4*)(nidx + (size_t)b * S);
        const int4 a = np[0], c = np[1], d = np[2], e = np[3];
        g_mark[a.x] = 1; g_mark[a.y] = 1; g_mark[a.z] = 1; g_mark[a.w] = 1;
        g_mark[c.x] = 1; g_mark[c.y] = 1; g_mark[c.z] = 1; g_mark[c.w] = 1;
        g_mark[d.x] = 1; g_mark[d.y] = 1; g_mark[d.z] = 1; g_mark[d.w] = 1;
        g_mark[e.x] = 1; g_mark[e.y] = 1; g_mark[e.z] = 1; g_mark[e.w] = 1;
    }

    grid_bar(2 * NBLK1);      // marks visible everywhere

    // ---- phase 2: compact (GT_ALL > NNODES -> single pass, full-warp ballot) ----
    {
        const bool m = (gt < NNODES) && (g_mark[gt] != 0);
        const unsigned mask = __ballot_sync(0xFFFFFFFFu, m);
        const int lane = tid & 31;
        int base = 0;
        if (lane == 0 && mask) base = atomicAdd(&g_ctrs[0], __popc(mask));
        base = __shfl_sync(0xFFFFFFFFu, base, 0);
        if (m) g_list[base + __popc(mask & ((1u << lane) - 1))] = gt;
    }

    grid_bar(3 * NBLK1);      // g_list/g_cnt final everywhere

    const int cnt = *(volatile int*)&g_ctrs[0];
    const int ntiles = (cnt + TILE1 - 1) / TILE1;

    // ================= R10 main loop: 16 producer / 8 consumer warps =======
    if (tid < NP1) {
        for (int i = 0, tile = blockIdx.x; tile < ntiles; tile += gridDim.x, i++) {
            const int b = i & 1;
            if (i >= 2) BAR_SYNC(3 + b, NT1);
            char* Ahi = smem + L1_A0 + b * L1_ABUF;
            char* Alo = Ahi + L1_AHALF;
            const int slot0 = tile * TILE1;

            #pragma unroll
            for (int it = 0; it < 2; it++) {
                const int lin = tid + it * NP1;      // 0..1023
                const int nn  = lin >> 5;            // warp-uniform
                const int d4  = lin & 31;
                const int node = g_list[min(slot0 + nn, cnt - 1)];
                const int4* np = (const int4*)(nidx + (size_t)node * S);
                const int4 na = np[0], nb4 = np[1], nc = np[2], nd = np[3];
                const int nb[16] = {na.x, na.y, na.z, na.w, nb4.x, nb4.y, nb4.z, nb4.w,
                                    nc.x, nc.y, nc.z, nc.w, nd.x, nd.y, nd.z, nd.w};
                gather_split(x, nb, node, nn, d4, Ahi, Alo);
            }
            BAR_ARRIVE(1 + b, NT1);
        }
    } else {
        const int w  = (tid - NP1) >> 5;    // 0..7
        const int l  = tid & 31;
        const int qr = l >> 2, qc = l & 3;
        const int nbase = w * 16;

        for (int i = 0, tile = blockIdx.x; tile < ntiles; tile += gridDim.x, i++) {
            const int b = i & 1;
            BAR_SYNC(1 + b, NT1);
            const uint32_t aHi = sb + L1_A0 + b * L1_ABUF;
            const uint32_t aLo = aHi + L1_AHALF;
            const int slot0 = tile * TILE1;

            float acc[2][2][4];
            #pragma unroll
            for (int t = 0; t < 2; t++)
                #pragma unroll
                for (int j = 0; j < 2; j++)
                    #pragma unroll
                    for (int u = 0; u < 4; u++) acc[t][j][u] = 0.f;

            #pragma unroll 2
            for (int ks = 0; ks < 16; ks++) {
                const int k0 = ks * 16;
                uint32_t ah[2][4], al[2][4];
                #pragma unroll
                for (int t = 0; t < 2; t++) {
                    const uint32_t r0 = (uint32_t)(t * 16 + qr) * (KSTR * 2);
                    const uint32_t r1 = r0 + 8 * (KSTR * 2);
                    const uint32_t cA = (uint32_t)(k0 + 2 * qc) * 2;
                    ah[t][0] = lds32(aHi + r0 + cA);  ah[t][1] = lds32(aHi + r1 + cA);
                    ah[t][2] = lds32(aHi + r0 + cA + 16); ah[t][3] = lds32(aHi + r1 + cA + 16);
                    al[t][0] = lds32(aLo + r0 + cA);  al[t][1] = lds32(aLo + r1 + cA);
                    al[t][2] = lds32(aLo + r0 + cA + 16); al[t][3] = lds32(aLo + r1 + cA + 16);
                }
                uint32_t bh[2][2], bl[2][2];
                #pragma unroll
                for (int j = 0; j < 2; j++) {
                    const uint32_t nrow = (uint32_t)(nbase + j * 8 + qr) * (KSTR * 2);
                    const uint32_t cB = (uint32_t)(k0 + 2 * qc) * 2;
                    bh[j][0] = lds32(sb + L1_BHI + nrow + cB);
                    bh[j][1] = lds32(sb + L1_BHI + nrow + cB + 16);
                    bl[j][0] = lds32(sb + L1_BLO + nrow + cB);
                    bl[j][1] = lds32(sb + L1_BLO + nrow + cB + 16);
                }
                #pragma unroll
                for (int t = 0; t < 2; t++)
                    #pragma unroll
                    for (int j = 0; j < 2; j++) {
                        mma_bf16(acc[t][j], ah[t][0], ah[t][1], ah[t][2], ah[t][3],
                                 bh[j][0], bh[j][1]);
                        mma_bf16(acc[t][j], ah[t][0], ah[t][1], ah[t][2], ah[t][3],
                                 bl[j][0], bl[j][1]);
                        mma_bf16(acc[t][j], al[t][0], al[t][1], al[t][2], al[t][3],
                                 bh[j][0], bh[j][1]);
                    }
            }
            BAR_ARRIVE(3 + b, NT1);

            #pragma unroll
            for (int t = 0; t < 2; t++) {
                const int nodeA = g_list[min(slot0 + t * 16 + qr, cnt - 1)];
                const int nodeB = g_list[min(slot0 + t * 16 + qr + 8, cnt - 1)];
                #pragma unroll
                for (int j = 0; j < 2; j++) {
                    const int n = nbase + j * 8 + 2 * qc;
                    const float bi0 = biass[n], bi1 = biass[n + 1];
                    float2 v0, v1;
                    v0.x = fmaxf(acc[t][j][0] + bi0, 0.f);
                    v0.y = fmaxf(acc[t][j][1] + bi1, 0.f);
                    v1.x = fmaxf(acc[t][j][2] + bi0, 0.f);
                    v1.y = fmaxf(acc[t][j][3] + bi1, 0.f);
                    *(float2*)(g_h1 + (size_t)nodeA * D + n) = v0;
                    *(float2*)(g_h1 + (size_t)nodeB * D + n) = v1;
                }
            }
        }
    }
}

// ---------------------------------------------------------------------------
// Layer 2: 32-node tile per block, grid=256, 2 blocks/SM (R11 proven).
// ---------------------------------------------------------------------------
extern "C" __global__ void __launch_bounds__(NT2, 2)
sage_layer2(const int* __restrict__ nidx, const int* __restrict__ batch,
            float* __restrict__ out)
{
    extern __shared__ char smem[];
    const uint32_t sb = smem_u32(smem);
    float* biass = (float*)(smem + L2_BIAS);

    const int tid = threadIdx.x;
    if (tid < 64) biass[tid] = g_b2p[tid];

    for (int i = tid; i < 256 * 64; i += NT2) {
        const int k = i >> 6, n = i & 63;
        const float w = g_W2p[i];
        const float h = bfr(w);
        *(__nv_bfloat16*)(smem + L2_BHI + (n * KSTR + k) * 2) = __float2bfloat16_rn(w);
        *(__nv_bfloat16*)(smem + L2_BLO + (n * KSTR + k) * 2) = __float2bfloat16_rn(w - h);
    }

    char* Ahi = smem + L2_AHI;
    char* Alo = smem + L2_ALO;
    const int pos0 = blockIdx.x * TILE2;
    #pragma unroll
    for (int it = 0; it < 2; it++) {
        const int lin = tid + it * NT2;      // 0..1023 float4 items
        const int nn  = lin >> 5;            // node 0..31 (warp-uniform)
        const int d4  = lin & 31;
        const int bnode = __ldg(batch + pos0 + nn);
        const int4* np = (const int4*)(nidx + (size_t)bnode * S);
        const int4 na = np[0], nb4 = np[1], nc = np[2], nd = np[3];
        const int nb[16] = {na.x, na.y, na.z, na.w, nb4.x, nb4.y, nb4.z, nb4.w,
                            nc.x, nc.y, nc.z, nc.w, nd.x, nd.y, nd.z, nd.w};
        gather_split(g_h1, nb, bnode, nn, d4, Ahi, Alo);
    }
    __syncthreads();

    const int w  = tid >> 5;
    const int l  = tid & 31;
    const int qr = l >> 2, qc = l & 3;
    const int mt = w >> 3;
    const int nbase = (w & 7) * 8;

    const uint32_t aHi = sb + L2_AHI;
    const uint32_t aLo = sb + L2_ALO;

    float acc[4];
    #pragma unroll
    for (int u = 0; u < 4; u++) acc[u] = 0.f;

    #pragma unroll 4
    for (int ks = 0; ks < 16; ks++) {
        const int k0 = ks * 16;
        uint32_t ah[4], al[4];
        {
            const uint32_t r0 = (uint32_t)(mt * 16 + qr) * (KSTR * 2);
            const uint32_t r1 = r0 + 8 * (KSTR * 2);
            const uint32_t cA = (uint32_t)(k0 + 2 * qc) * 2;
            ah[0] = lds32(aHi + r0 + cA);      ah[1] = lds32(aHi + r1 + cA);
            ah[2] = lds32(aHi + r0 + cA + 16); ah[3] = lds32(aHi + r1 + cA + 16);
            al[0] = lds32(aLo + r0 + cA);      al[1] = lds32(aLo + r1 + cA);
            al[2] = lds32(aLo + r0 + cA + 16); al[3] = lds32(aLo + r1 + cA + 16);
        }
        uint32_t bh[2], bl[2];
        {
            const uint32_t nrow = (uint32_t)(nbase + qr) * (KSTR * 2);
            const uint32_t cB = (uint32_t)(k0 + 2 * qc) * 2;
            bh[0] = lds32(sb + L2_BHI + nrow + cB);
            bh[1] = lds32(sb + L2_BHI + nrow + cB + 16);
            bl[0] = lds32(sb + L2_BLO + nrow + cB);
            bl[1] = lds32(sb + L2_BLO + nrow + cB + 16);
        }
        mma_bf16(acc, ah[0], ah[1], ah[2], ah[3], bh[0], bh[1]);
        mma_bf16(acc, ah[0], ah[1], ah[2], ah[3], bl[0], bl[1]);
        mma_bf16(acc, al[0], al[1], al[2], al[3], bh[0], bh[1]);
    }

    const int r0 = pos0 + mt * 16 + qr;
    const int n = nbase + 2 * qc;
    const float bi0 = biass[n], bi1 = biass[n + 1];
    float2 v0, v1;
    v0.x = acc[0] + bi0; v0.y = acc[1] + bi1;
    v1.x = acc[2] + bi0; v1.y = acc[3] + bi1;
    *(float2*)(out + (size_t)r0 * 64 + n) = v0;
    *(float2*)(out + (size_t)(r0 + 8) * 64 + n) = v1;
}

// ---------------------------------------------------------------------------
extern "C" void kernel_launch(void* const* d_in, const int* in_sizes, int n_in,
                              void* d_out, int out_size)
{
    const float* x    = (const float*)d_in[0];
    const int*   nidx = (const int*)  d_in[1];
    const int*   batch= (const int*)  d_in[2];
    const float* W1   = (const float*)d_in[3];
    const float* b1   = (const float*)d_in[4];
    const float* W2   = (const float*)d_in[5];
    const float* b2   = (const float*)d_in[6];
    const float* Wout = (const float*)d_in[7];
    const float* bout = (const float*)d_in[8];
    float* out = (float*)d_out;

    cudaFuncSetAttribute((const void*)sage_layer1,
                         cudaFuncAttributeMaxDynamicSharedMemorySize, SMEM1_SZ);
    cudaFuncSetAttribute((const void*)sage_layer2,
                         cudaFuncAttributeMaxDynamicSharedMemorySize, SMEM2_SZ);

    void* p_ctrs;
    cudaGetSymbolAddress(&p_ctrs, g_ctrs);
    cudaMemsetAsync(p_ctrs, 0, 2 * sizeof(int));

    sage_layer1<<<NBLK1, NT1, SMEM1_SZ>>>(x, nidx, batch, W1, b1,
                                          W2, b2, Wout, bout);
    sage_layer2<<<256, NT2, SMEM2_SZ>>>(nidx, batch, out);
}

// round 16
// speedup vs baseline: 1.0851x; 1.0851x over previous
#include <cuda_runtime.h>
#include <cuda_bf16.h>
#include <cstdint>

#define NNODES 100000
#define D      128
#define S      16
#define NBATCH 8192
#define NT1    768
#define NP1    512                   // 16 producer warps, 8 consumer warps

#define TILE1  32
#define KSTR   264                   // bf16 row stride (256 + 8 pad)

// ---- layer-1 smem offsets ----
#define L1_BHI   0
#define L1_BLO   67584
#define L1_A0    135168
#define L1_ABUF  33792
#define L1_AHALF 16896
#define L1_BIAS  202752
#define SMEM1_SZ 203264

// ---- layer-2 smem offsets (32-node tile, 2 blocks/SM) ----
#define L2_BHI   0
#define L2_BLO   33792
#define L2_AHI   67584
#define L2_ALO   84480
#define L2_BIAS  101376
#define SMEM2_SZ 101632
#define NT2      512
#define TILE2    32

#define NREF (NBATCH * 17)           // 139264 = 544 * 256 exactly

__device__ float g_h1[(size_t)NNODES * D];
__device__ float g_W2p[256 * 64];
__device__ float g_b2p[64];
__device__ unsigned g_mark[NNODES / 4];   // byte flags accessed as u32 words
__device__ int  g_list[NNODES];
__device__ int  g_cnt;

// ---------------- helpers ----------------
__device__ __forceinline__ uint32_t pbf2(float lo, float hi) {
    uint32_t r;
    asm("cvt.rn.bf16x2.f32 %0, %1, %2;" : "=r"(r) : "f"(hi), "f"(lo));
    return r;
}
__device__ __forceinline__ float bfr(float f) {
    return __bfloat162float(__float2bfloat16_rn(f));
}
__device__ __forceinline__ uint32_t lds32(uint32_t a) {
    uint32_t v; asm volatile("ld.shared.b32 %0, [%1];" : "=r"(v) : "r"(a)); return v;
}
__device__ __forceinline__ uint32_t smem_u32(const void* p) {
    uint32_t a;
    asm("{ .reg .u64 t; cvta.to.shared.u64 t, %1; cvt.u32.u64 %0, t; }"
        : "=r"(a) : "l"(p));
    return a;
}
__device__ __forceinline__ void mma_bf16(float c[4], uint32_t a0, uint32_t a1,
                                         uint32_t a2, uint32_t a3,
                                         uint32_t b0, uint32_t b1) {
    asm volatile(
        "mma.sync.aligned.m16n8k16.row.col.f32.bf16.bf16.f32 "
        "{%0,%1,%2,%3}, {%4,%5,%6,%7}, {%8,%9}, {%0,%1,%2,%3};"
        : "+f"(c[0]), "+f"(c[1]), "+f"(c[2]), "+f"(c[3])
        : "r"(a0), "r"(a1), "r"(a2), "r"(a3), "r"(b0), "r"(b1));
}

#define BAR_SYNC(id, n)   asm volatile("bar.sync %0, %1;"   :: "r"(id), "r"(n) : "memory")
#define BAR_ARRIVE(id, n) asm volatile("bar.arrive %0, %1;" :: "r"(id), "r"(n) : "memory")

// float4-granularity gather+split (R10-proven)
__device__ __forceinline__ void gather_split(
    const float* __restrict__ src, const int* nb, int node, int nn, int d4,
    char* Ahi, char* Alo)
{
    const float4 self = *((const float4*)(src + (size_t)node * D) + d4);
    float4 m = *((const float4*)(src + (size_t)nb[0] * D) + d4);
    #pragma unroll
    for (int s = 1; s < S; s++) {
        float4 v = *((const float4*)(src + (size_t)nb[s] * D) + d4);
        m.x = fmaxf(m.x, v.x); m.y = fmaxf(m.y, v.y);
        m.z = fmaxf(m.z, v.z); m.w = fmaxf(m.w, v.w);
    }
    const int ks = d4 * 4;
    const int ka = D + ks;
    uint2 v;
    v.x = pbf2(self.x, self.y); v.y = pbf2(self.z, self.w);
    *(uint2*)(Ahi + (nn * KSTR + ks) * 2) = v;
    v.x = pbf2(self.x - bfr(self.x), self.y - bfr(self.y));
    v.y = pbf2(self.z - bfr(self.z), self.w - bfr(self.w));
    *(uint2*)(Alo + (nn * KSTR + ks) * 2) = v;
    v.x = pbf2(m.x, m.y); v.y = pbf2(m.z, m.w);
    *(uint2*)(Ahi + (nn * KSTR + ka) * 2) = v;
    v.x = pbf2(m.x - bfr(m.x), m.y - bfr(m.y));
    v.y = pbf2(m.z - bfr(m.z), m.w - bfr(m.w));
    *(uint2*)(Alo + (nn * KSTR + ka) * 2) = v;
}

// ---------------------------------------------------------------------------
// frontier_prep: blocks 0-63 = W2p/b2p prep; blocks 64-607 = mark+append.
// One reference per thread; atomicOr dedup + warp-aggregated list append.
// ---------------------------------------------------------------------------
extern "C" __global__ void __launch_bounds__(256, 1)
frontier_prep(const int* __restrict__ batch, const int* __restrict__ nidx,
              const float* __restrict__ W2, const float* __restrict__ b2,
              const float* __restrict__ Wout, const float* __restrict__ bout)
{
    __shared__ float Wo[128 * 64];
    const int tid = threadIdx.x;

    if (blockIdx.x < 64) {
        for (int i = tid; i < 128 * 64 / 4; i += 256)
            ((float4*)Wo)[i] = ((const float4*)Wout)[i];
        __syncthreads();

        const int k = blockIdx.x * 4 + (tid >> 6);
        const int n = tid & 63;
        const float* w2r = W2 + k * 128;
        float s0 = 0.f, s1 = 0.f, s2 = 0.f, s3 = 0.f;
        #pragma unroll 8
        for (int j = 0; j < 128; j += 4) {
            s0 += w2r[j + 0] * Wo[(j + 0) * 64 + n];
            s1 += w2r[j + 1] * Wo[(j + 1) * 64 + n];
            s2 += w2r[j + 2] * Wo[(j + 2) * 64 + n];
            s3 += w2r[j + 3] * Wo[(j + 3) * 64 + n];
        }
        g_W2p[k * 64 + n] = (s0 + s1) + (s2 + s3);

        if (blockIdx.x == 0 && tid < 64) {
            float t = bout[tid];
            #pragma unroll 8
            for (int j = 0; j < 128; j++) t += b2[j] * Wo[j * 64 + tid];
            g_b2p[tid] = t;
        }
    } else {
        // idx in [0, NREF); NREF = 544 * 256 exactly -> no tail, ballot safe
        const int idx = (blockIdx.x - 64) * 256 + tid;
        const int bi = idx / 17;
        const int r  = idx - bi * 17;
        const int b  = __ldg(batch + bi);
        const int node = (r == 0) ? b : __ldg(nidx + (size_t)b * S + (r - 1));

        const int shift = (node & 3) * 8;
        const unsigned old = atomicOr(&g_mark[node >> 2], 1u << shift);
        const bool add = ((old >> shift) & 0xFFu) == 0u;
        const unsigned mask = __ballot_sync(0xFFFFFFFFu, add);
        const int lane = tid & 31;
        int base = 0;
        if (lane == 0 && mask) base = atomicAdd(&g_cnt, __popc(mask));
        base = __shfl_sync(0xFFFFFFFFu, base, 0);
        if (add) g_list[base + __popc(mask & ((1u << lane) - 1))] = node;
    }
}

// ---------------------------------------------------------------------------
// Layer 1 over the compacted frontier: EXACT R10 (16 producer / 8 consumer).
// ---------------------------------------------------------------------------
extern "C" __global__ void __launch_bounds__(NT1, 1)
sage_layer1(const float* __restrict__ x, const int* __restrict__ nidx,
            const float* __restrict__ W1, const float* __restrict__ b1)
{
    extern __shared__ char smem[];
    const uint32_t sb = smem_u32(smem);
    float* biass = (float*)(smem + L1_BIAS);

    const int tid = threadIdx.x;
    if (tid < 128) biass[tid] = b1[tid];

    for (int i = tid; i < 256 * 128; i += NT1) {
        const int k = i >> 7, n = i & 127;
        const float w = W1[(size_t)k * 128 + n];
        const float h = bfr(w);
        *(__nv_bfloat16*)(smem + L1_BHI + (n * KSTR + k) * 2) = __float2bfloat16_rn(w);
        *(__nv_bfloat16*)(smem + L1_BLO + (n * KSTR + k) * 2) = __float2bfloat16_rn(w - h);
    }
    __syncthreads();

    const int cnt = *(const volatile int*)&g_cnt;
    const int ntiles = (cnt + TILE1 - 1) / TILE1;

    if (tid < NP1) {
        // ============ PRODUCERS (warps 0-15): 2 float4 items each ============
        for (int i = 0, tile = blockIdx.x; tile < ntiles; tile += gridDim.x, i++) {
            const int b = i & 1;
            if (i >= 2) BAR_SYNC(3 + b, NT1);
            char* Ahi = smem + L1_A0 + b * L1_ABUF;
            char* Alo = Ahi + L1_AHALF;
            const int slot0 = tile * TILE1;

            #pragma unroll
            for (int it = 0; it < 2; it++) {
                const int lin = tid + it * NP1;      // 0..1023
                const int nn  = lin >> 5;            // warp-uniform
                const int d4  = lin & 31;
                const int node = g_list[min(slot0 + nn, cnt - 1)];
                const int4* np = (const int4*)(nidx + (size_t)node * S);
                const int4 na = np[0], nb4 = np[1], nc = np[2], nd = np[3];
                const int nb[16] = {na.x, na.y, na.z, na.w, nb4.x, nb4.y, nb4.z, nb4.w,
                                    nc.x, nc.y, nc.z, nc.w, nd.x, nd.y, nd.z, nd.w};
                gather_split(x, nb, node, nn, d4, Ahi, Alo);
            }
            BAR_ARRIVE(1 + b, NT1);
        }
    } else {
        // ============ CONSUMERS (warps 16-23): m32 x n16 each ============
        const int w  = (tid - NP1) >> 5;    // 0..7
        const int l  = tid & 31;
        const int qr = l >> 2, qc = l & 3;
        const int nbase = w * 16;

        for (int i = 0, tile = blockIdx.x; tile < ntiles; tile += gridDim.x, i++) {
            const int b = i & 1;
            BAR_SYNC(1 + b, NT1);
            const uint32_t aHi = sb + L1_A0 + b * L1_ABUF;
            const uint32_t aLo = aHi + L1_AHALF;
            const int slot0 = tile * TILE1;

            float acc[2][2][4];
            #pragma unroll
            for (int t = 0; t < 2; t++)
                #pragma unroll
                for (int j = 0; j < 2; j++)
                    #pragma unroll
                    for (int u = 0; u < 4; u++) acc[t][j][u] = 0.f;

            #pragma unroll 2
            for (int ks = 0; ks < 16; ks++) {
                const int k0 = ks * 16;
                uint32_t ah[2][4], al[2][4];
                #pragma unroll
                for (int t = 0; t < 2; t++) {
                    const uint32_t r0 = (uint32_t)(t * 16 + qr) * (KSTR * 2);
                    const uint32_t r1 = r0 + 8 * (KSTR * 2);
                    const uint32_t cA = (uint32_t)(k0 + 2 * qc) * 2;
                    ah[t][0] = lds32(aHi + r0 + cA);  ah[t][1] = lds32(aHi + r1 + cA);
                    ah[t][2] = lds32(aHi + r0 + cA + 16); ah[t][3] = lds32(aHi + r1 + cA + 16);
                    al[t][0] = lds32(aLo + r0 + cA);  al[t][1] = lds32(aLo + r1 + cA);
                    al[t][2] = lds32(aLo + r0 + cA + 16); al[t][3] = lds32(aLo + r1 + cA + 16);
                }
                uint32_t bh[2][2], bl[2][2];
                #pragma unroll
                for (int j = 0; j < 2; j++) {
                    const uint32_t nrow = (uint32_t)(nbase + j * 8 + qr) * (KSTR * 2);
                    const uint32_t cB = (uint32_t)(k0 + 2 * qc) * 2;
                    bh[j][0] = lds32(sb + L1_BHI + nrow + cB);
                    bh[j][1] = lds32(sb + L1_BHI + nrow + cB + 16);
                    bl[j][0] = lds32(sb + L1_BLO + nrow + cB);
                    bl[j][1] = lds32(sb + L1_BLO + nrow + cB + 16);
                }
                #pragma unroll
                for (int t = 0; t < 2; t++)
                    #pragma unroll
                    for (int j = 0; j < 2; j++) {
                        mma_bf16(acc[t][j], ah[t][0], ah[t][1], ah[t][2], ah[t][3],
                                 bh[j][0], bh[j][1]);
                        mma_bf16(acc[t][j], ah[t][0], ah[t][1], ah[t][2], ah[t][3],
                                 bl[j][0], bl[j][1]);
                        mma_bf16(acc[t][j], al[t][0], al[t][1], al[t][2], al[t][3],
                                 bh[j][0], bh[j][1]);
                    }
            }
            BAR_ARRIVE(3 + b, NT1);

            #pragma unroll
            for (int t = 0; t < 2; t++) {
                const int nodeA = g_list[min(slot0 + t * 16 + qr, cnt - 1)];
                const int nodeB = g_list[min(slot0 + t * 16 + qr + 8, cnt - 1)];
                #pragma unroll
                for (int j = 0; j < 2; j++) {
                    const int n = nbase + j * 8 + 2 * qc;
                    const float bi0 = biass[n], bi1 = biass[n + 1];
                    float2 v0, v1;
                    v0.x = fmaxf(acc[t][j][0] + bi0, 0.f);
                    v0.y = fmaxf(acc[t][j][1] + bi1, 0.f);
                    v1.x = fmaxf(acc[t][j][2] + bi0, 0.f);
                    v1.y = fmaxf(acc[t][j][3] + bi1, 0.f);
                    *(float2*)(g_h1 + (size_t)nodeA * D + n) = v0;
                    *(float2*)(g_h1 + (size_t)nodeB * D + n) = v1;
                }
            }
        }
    }
}

// ---------------------------------------------------------------------------
// Layer 2: 32-node tile per block, grid=256, 2 blocks/SM (EXACT R11).
// ---------------------------------------------------------------------------
extern "C" __global__ void __launch_bounds__(NT2, 2)
sage_layer2(const int* __restrict__ nidx, const int* __restrict__ batch,
            float* __restrict__ out)
{
    extern __shared__ char smem[];
    const uint32_t sb = smem_u32(smem);
    float* biass = (float*)(smem + L2_BIAS);

    const int tid = threadIdx.x;
    if (tid < 64) biass[tid] = g_b2p[tid];

    for (int i = tid; i < 256 * 64; i += NT2) {
        const int k = i >> 6, n = i & 63;
        const float w = g_W2p[i];
        const float h = bfr(w);
        *(__nv_bfloat16*)(smem + L2_BHI + (n * KSTR + k) * 2) = __float2bfloat16_rn(w);
        *(__nv_bfloat16*)(smem + L2_BLO + (n * KSTR + k) * 2) = __float2bfloat16_rn(w - h);
    }

    char* Ahi = smem + L2_AHI;
    char* Alo = smem + L2_ALO;
    const int pos0 = blockIdx.x * TILE2;
    #pragma unroll
    for (int it = 0; it < 2; it++) {
        const int lin = tid + it * NT2;      // 0..1023 float4 items
        const int nn  = lin >> 5;            // node 0..31 (warp-uniform)
        const int d4  = lin & 31;
        const int bnode = __ldg(batch + pos0 + nn);
        const int4* np = (const int4*)(nidx + (size_t)bnode * S);
        const int4 na = np[0], nb4 = np[1], nc = np[2], nd = np[3];
        const int nb[16] = {na.x, na.y, na.z, na.w, nb4.x, nb4.y, nb4.z, nb4.w,
                            nc.x, nc.y, nc.z, nc.w, nd.x, nd.y, nd.z, nd.w};
        gather_split(g_h1, nb, bnode, nn, d4, Ahi, Alo);
    }
    __syncthreads();

    const int w  = tid >> 5;
    const int l  = tid & 31;
    const int qr = l >> 2, qc = l & 3;
    const int mt = w >> 3;
    const int nbase = (w & 7) * 8;

    const uint32_t aHi = sb + L2_AHI;
    const uint32_t aLo = sb + L2_ALO;

    float acc[4];
    #pragma unroll
    for (int u = 0; u < 4; u++) acc[u] = 0.f;

    #pragma unroll 4
    for (int ks = 0; ks < 16; ks++) {
        const int k0 = ks * 16;
        uint32_t ah[4], al[4];
        {
            const uint32_t r0 = (uint32_t)(mt * 16 + qr) * (KSTR * 2);
            const uint32_t r1 = r0 + 8 * (KSTR * 2);
            const uint32_t cA = (uint32_t)(k0 + 2 * qc) * 2;
            ah[0] = lds32(aHi + r0 + cA);      ah[1] = lds32(aHi + r1 + cA);
            ah[2] = lds32(aHi + r0 + cA + 16); ah[3] = lds32(aHi + r1 + cA + 16);
            al[0] = lds32(aLo + r0 + cA);      al[1] = lds32(aLo + r1 + cA);
            al[2] = lds32(aLo + r0 + cA + 16); al[3] = lds32(aLo + r1 + cA + 16);
        }
        uint32_t bh[2], bl[2];
        {
            const uint32_t nrow = (uint32_t)(nbase + qr) * (KSTR * 2);
            const uint32_t cB = (uint32_t)(k0 + 2 * qc) * 2;
            bh[0] = lds32(sb + L2_BHI + nrow + cB);
            bh[1] = lds32(sb + L2_BHI + nrow + cB + 16);
            bl[0] = lds32(sb + L2_BLO + nrow + cB);
            bl[1] = lds32(sb + L2_BLO + nrow + cB + 16);
        }
        mma_bf16(acc, ah[0], ah[1], ah[2], ah[3], bh[0], bh[1]);
        mma_bf16(acc, ah[0], ah[1], ah[2], ah[3], bl[0], bl[1]);
        mma_bf16(acc, al[0], al[1], al[2], al[3], bh[0], bh[1]);
    }

    const int r0 = pos0 + mt * 16 + qr;
    const int n = nbase + 2 * qc;
    const float bi0 = biass[n], bi1 = biass[n + 1];
    float2 v0, v1;
    v0.x = acc[0] + bi0; v0.y = acc[1] + bi1;
    v1.x = acc[2] + bi0; v1.y = acc[3] + bi1;
    *(float2*)(out + (size_t)r0 * 64 + n) = v0;
    *(float2*)(out + (size_t)(r0 + 8) * 64 + n) = v1;
}

// ---------------------------------------------------------------------------
extern "C" void kernel_launch(void* const* d_in, const int* in_sizes, int n_in,
                              void* d_out, int out_size)
{
    const float* x    = (const float*)d_in[0];
    const int*   nidx = (const int*)  d_in[1];
    const int*   batch= (const int*)  d_in[2];
    const float* W1   = (const float*)d_in[3];
    const float* b1   = (const float*)d_in[4];
    const float* W2   = (const float*)d_in[5];
    const float* b2   = (const float*)d_in[6];
    const float* Wout = (const float*)d_in[7];
    const float* bout = (const float*)d_in[8];
    float* out = (float*)d_out;

    cudaFuncSetAttribute((const void*)sage_layer1,
                         cudaFuncAttributeMaxDynamicSharedMemorySize, SMEM1_SZ);
    cudaFuncSetAttribute((const void*)sage_layer2,
                         cudaFuncAttributeMaxDynamicSharedMemorySize, SMEM2_SZ);

    void* p_mark; void* p_cnt;
    cudaGetSymbolAddress(&p_mark, g_mark);
    cudaGetSymbolAddress(&p_cnt,  g_cnt);
    cudaMemsetAsync(p_mark, 0, NNODES);          // NNODES bytes = NNODES/4 words
    cudaMemsetAsync(p_cnt,  0, sizeof(int));

    frontier_prep<<<64 + NREF / 256, 256>>>(batch, nidx, W2, b2, Wout, bout);
    sage_layer1<<<152, NT1, SMEM1_SZ>>>(x, nidx, W1, b1);
    sage_layer2<<<256, NT2, SMEM2_SZ>>>(nidx, batch, out);
}

// round 17
// speedup vs baseline: 1.1387x; 1.0494x over previous
#include <cuda_runtime.h>
#include <cuda_bf16.h>
#include <cstdint>

#define NNODES 100000
#define D      128
#define S      16
#define NBATCH 8192
#define NT1    768
#define NP1    512                   // 16 producer warps, 8 consumer warps

#define TILE1  32
#define KSTR   264                   // bf16 row stride (256 + 8 pad)

// ---- layer-1 smem offsets ----
#define L1_BHI   0
#define L1_BLO   67584
#define L1_A0    135168
#define L1_ABUF  33792
#define L1_AHALF 16896
#define L1_BIAS  202752
#define SMEM1_SZ 203264

// ---- layer-2 smem offsets (32-node tile, 2 blocks/SM) ----
#define L2_BHI   0
#define L2_BLO   33792
#define L2_AHI   67584
#define L2_ALO   84480
#define L2_BIAS  101376
#define SMEM2_SZ 101632
#define NT2      512
#define TILE2    32

#define NREF (NBATCH * 17)           // 139264 = 544 * 256 exactly

__device__ float g_h1[(size_t)NNODES * D];
__device__ float g_W2p[256 * 64];
__device__ float g_b2p[64];
__device__ unsigned g_mark[NNODES / 4];   // byte flags accessed as u32 words
__device__ int  g_list[NNODES];
__device__ int  g_cnt;

// ---------------- helpers ----------------
__device__ __forceinline__ uint32_t pbf2(float lo, float hi) {
    uint32_t r;
    asm("cvt.rn.bf16x2.f32 %0, %1, %2;" : "=r"(r) : "f"(hi), "f"(lo));
    return r;
}
__device__ __forceinline__ float bfr(float f) {
    return __bfloat162float(__float2bfloat16_rn(f));
}
__device__ __forceinline__ uint32_t lds32(uint32_t a) {
    uint32_t v; asm volatile("ld.shared.b32 %0, [%1];" : "=r"(v) : "r"(a)); return v;
}
__device__ __forceinline__ uint32_t smem_u32(const void* p) {
    uint32_t a;
    asm("{ .reg .u64 t; cvta.to.shared.u64 t, %1; cvt.u32.u64 %0, t; }"
        : "=r"(a) : "l"(p));
    return a;
}
__device__ __forceinline__ void mma_bf16(float c[4], uint32_t a0, uint32_t a1,
                                         uint32_t a2, uint32_t a3,
                                         uint32_t b0, uint32_t b1) {
    asm volatile(
        "mma.sync.aligned.m16n8k16.row.col.f32.bf16.bf16.f32 "
        "{%0,%1,%2,%3}, {%4,%5,%6,%7}, {%8,%9}, {%0,%1,%2,%3};"
        : "+f"(c[0]), "+f"(c[1]), "+f"(c[2]), "+f"(c[3])
        : "r"(a0), "r"(a1), "r"(a2), "r"(a3), "r"(b0), "r"(b1));
}

#define BAR_SYNC(id, n)   asm volatile("bar.sync %0, %1;"   :: "r"(id), "r"(n) : "memory")
#define BAR_ARRIVE(id, n) asm volatile("bar.arrive %0, %1;" :: "r"(id), "r"(n) : "memory")

// float4-granularity gather+split (R10-proven)
__device__ __forceinline__ void gather_split(
    const float* __restrict__ src, const int* nb, int node, int nn, int d4,
    char* Ahi, char* Alo)
{
    const float4 self = *((const float4*)(src + (size_t)node * D) + d4);
    float4 m = *((const float4*)(src + (size_t)nb[0] * D) + d4);
    #pragma unroll
    for (int s = 1; s < S; s++) {
        float4 v = *((const float4*)(src + (size_t)nb[s] * D) + d4);
        m.x = fmaxf(m.x, v.x); m.y = fmaxf(m.y, v.y);
        m.z = fmaxf(m.z, v.z); m.w = fmaxf(m.w, v.w);
    }
    const int ks = d4 * 4;
    const int ka = D + ks;
    uint2 v;
    v.x = pbf2(self.x, self.y); v.y = pbf2(self.z, self.w);
    *(uint2*)(Ahi + (nn * KSTR + ks) * 2) = v;
    v.x = pbf2(self.x - bfr(self.x), self.y - bfr(self.y));
    v.y = pbf2(self.z - bfr(self.z), self.w - bfr(self.w));
    *(uint2*)(Alo + (nn * KSTR + ks) * 2) = v;
    v.x = pbf2(m.x, m.y); v.y = pbf2(m.z, m.w);
    *(uint2*)(Ahi + (nn * KSTR + ka) * 2) = v;
    v.x = pbf2(m.x - bfr(m.x), m.y - bfr(m.y));
    v.y = pbf2(m.z - bfr(m.z), m.w - bfr(m.w));
    *(uint2*)(Alo + (nn * KSTR + ka) * 2) = v;
}

// ---------------------------------------------------------------------------
// mark_frontier: one reference per thread; atomicOr dedup + block-aggregated
// list append (ONE global atomicAdd per block instead of one per warp).
// ---------------------------------------------------------------------------
extern "C" __global__ void __launch_bounds__(256, 1)
mark_frontier(const int* __restrict__ batch, const int* __restrict__ nidx)
{
    __shared__ int scnt, sbase;
    const int tid = threadIdx.x;
    if (tid == 0) scnt = 0;
    __syncthreads();

    const int idx = blockIdx.x * 256 + tid;   // < NREF exactly
    const int bi = idx / 17;
    const int r  = idx - bi * 17;
    const int b  = __ldg(batch + bi);
    const int node = (r == 0) ? b : __ldg(nidx + (size_t)b * S + (r - 1));

    const int shift = (node & 3) * 8;
    const unsigned old = atomicOr(&g_mark[node >> 2], 1u << shift);
    const bool add = ((old >> shift) & 0xFFu) == 0u;
    int local = 0;
    if (add) local = atomicAdd(&scnt, 1);
    __syncthreads();
    if (tid == 0 && scnt) sbase = atomicAdd(&g_cnt, scnt);
    __syncthreads();
    if (add) g_list[sbase + local] = node;
}

// ---------------------------------------------------------------------------
// Layer 1: R10 main loop (16 producer / 8 consumer warps). Consumer warps
// additionally compute W2p/b2p as a pre-loop prologue (blocks 0-128).
// ---------------------------------------------------------------------------
extern "C" __global__ void __launch_bounds__(NT1, 1)
sage_layer1(const float* __restrict__ x, const int* __restrict__ nidx,
            const float* __restrict__ W1, const float* __restrict__ b1,
            const float* __restrict__ W2, const float* __restrict__ b2,
            const float* __restrict__ Wout, const float* __restrict__ bout)
{
    extern __shared__ char smem[];
    const uint32_t sb = smem_u32(smem);
    float* biass = (float*)(smem + L1_BIAS);

    const int tid = threadIdx.x;
    if (tid < 128) biass[tid] = b1[tid];

    for (int i = tid; i < 256 * 128; i += NT1) {
        const int k = i >> 7, n = i & 127;
        const float w = W1[(size_t)k * 128 + n];
        const float h = bfr(w);
        *(__nv_bfloat16*)(smem + L1_BHI + (n * KSTR + k) * 2) = __float2bfloat16_rn(w);
        *(__nv_bfloat16*)(smem + L1_BLO + (n * KSTR + k) * 2) = __float2bfloat16_rn(w - h);
    }
    __syncthreads();

    const int cnt = *(const volatile int*)&g_cnt;
    const int ntiles = (cnt + TILE1 - 1) / TILE1;

    if (tid < NP1) {
        // ============ PRODUCERS (warps 0-15): 2 float4 items each ============
        for (int i = 0, tile = blockIdx.x; tile < ntiles; tile += gridDim.x, i++) {
            const int b = i & 1;
            if (i >= 2) BAR_SYNC(3 + b, NT1);
            char* Ahi = smem + L1_A0 + b * L1_ABUF;
            char* Alo = Ahi + L1_AHALF;
            const int slot0 = tile * TILE1;

            #pragma unroll
            for (int it = 0; it < 2; it++) {
                const int lin = tid + it * NP1;      // 0..1023
                const int nn  = lin >> 5;            // warp-uniform
                const int d4  = lin & 31;
                const int node = g_list[min(slot0 + nn, cnt - 1)];
                const int4* np = (const int4*)(nidx + (size_t)node * S);
                const int4 na = np[0], nb4 = np[1], nc = np[2], nd = np[3];
                const int nb[16] = {na.x, na.y, na.z, na.w, nb4.x, nb4.y, nb4.z, nb4.w,
                                    nc.x, nc.y, nc.z, nc.w, nd.x, nd.y, nd.z, nd.w};
                gather_split(x, nb, node, nn, d4, Ahi, Alo);
            }
            BAR_ARRIVE(1 + b, NT1);
        }
    } else {
        const int tid2 = tid - NP1;   // 0..255

        // ---- prologue: W2p = W2 @ Wout (blocks 0-127, 128 outputs each),
        //      b2p (block 128). Overlaps producers' first-tile gather. ----
        if (blockIdx.x < 128 && tid2 < 128) {
            const int o = blockIdx.x * 128 + tid2;   // 0..16383
            const int k = o >> 6, n = o & 63;
            const float* w2r = W2 + k * 128;
            float s0 = 0.f, s1 = 0.f, s2 = 0.f, s3 = 0.f;
            float s4 = 0.f, s5 = 0.f, s6 = 0.f, s7 = 0.f;
            #pragma unroll 4
            for (int j = 0; j < 128; j += 8) {
                s0 += w2r[j + 0] * Wout[(j + 0) * 64 + n];
                s1 += w2r[j + 1] * Wout[(j + 1) * 64 + n];
                s2 += w2r[j + 2] * Wout[(j + 2) * 64 + n];
                s3 += w2r[j + 3] * Wout[(j + 3) * 64 + n];
                s4 += w2r[j + 4] * Wout[(j + 4) * 64 + n];
                s5 += w2r[j + 5] * Wout[(j + 5) * 64 + n];
                s6 += w2r[j + 6] * Wout[(j + 6) * 64 + n];
                s7 += w2r[j + 7] * Wout[(j + 7) * 64 + n];
            }
            g_W2p[o] = ((s0 + s1) + (s2 + s3)) + ((s4 + s5) + (s6 + s7));
        }
        if (blockIdx.x == 128 && tid2 < 64) {
            float t = bout[tid2];
            float t0 = 0.f, t1 = 0.f;
            #pragma unroll 8
            for (int j = 0; j < 128; j += 2) {
                t0 += b2[j] * Wout[j * 64 + tid2];
                t1 += b2[j + 1] * Wout[(j + 1) * 64 + tid2];
            }
            g_b2p[tid2] = t + t0 + t1;
        }

        // ============ CONSUMERS (warps 16-23): m32 x n16 each ============
        const int w  = tid2 >> 5;    // 0..7
        const int l  = tid & 31;
        const int qr = l >> 2, qc = l & 3;
        const int nbase = w * 16;

        for (int i = 0, tile = blockIdx.x; tile < ntiles; tile += gridDim.x, i++) {
            const int b = i & 1;
            BAR_SYNC(1 + b, NT1);
            const uint32_t aHi = sb + L1_A0 + b * L1_ABUF;
            const uint32_t aLo = aHi + L1_AHALF;
            const int slot0 = tile * TILE1;

            float acc[2][2][4];
            #pragma unroll
            for (int t = 0; t < 2; t++)
                #pragma unroll
                for (int j = 0; j < 2; j++)
                    #pragma unroll
                    for (int u = 0; u < 4; u++) acc[t][j][u] = 0.f;

            #pragma unroll 2
            for (int ks = 0; ks < 16; ks++) {
                const int k0 = ks * 16;
                uint32_t ah[2][4], al[2][4];
                #pragma unroll
                for (int t = 0; t < 2; t++) {
                    const uint32_t r0 = (uint32_t)(t * 16 + qr) * (KSTR * 2);
                    const uint32_t r1 = r0 + 8 * (KSTR * 2);
                    const uint32_t cA = (uint32_t)(k0 + 2 * qc) * 2;
                    ah[t][0] = lds32(aHi + r0 + cA);  ah[t][1] = lds32(aHi + r1 + cA);
                    ah[t][2] = lds32(aHi + r0 + cA + 16); ah[t][3] = lds32(aHi + r1 + cA + 16);
                    al[t][0] = lds32(aLo + r0 + cA);  al[t][1] = lds32(aLo + r1 + cA);
                    al[t][2] = lds32(aLo + r0 + cA + 16); al[t][3] = lds32(aLo + r1 + cA + 16);
                }
                uint32_t bh[2][2], bl[2][2];
                #pragma unroll
                for (int j = 0; j < 2; j++) {
                    const uint32_t nrow = (uint32_t)(nbase + j * 8 + qr) * (KSTR * 2);
                    const uint32_t cB = (uint32_t)(k0 + 2 * qc) * 2;
                    bh[j][0] = lds32(sb + L1_BHI + nrow + cB);
                    bh[j][1] = lds32(sb + L1_BHI + nrow + cB + 16);
                    bl[j][0] = lds32(sb + L1_BLO + nrow + cB);
                    bl[j][1] = lds32(sb + L1_BLO + nrow + cB + 16);
                }
                #pragma unroll
                for (int t = 0; t < 2; t++)
                    #pragma unroll
                    for (int j = 0; j < 2; j++) {
                        mma_bf16(acc[t][j], ah[t][0], ah[t][1], ah[t][2], ah[t][3],
                                 bh[j][0], bh[j][1]);
                        mma_bf16(acc[t][j], ah[t][0], ah[t][1], ah[t][2], ah[t][3],
                                 bl[j][0], bl[j][1]);
                        mma_bf16(acc[t][j], al[t][0], al[t][1], al[t][2], al[t][3],
                                 bh[j][0], bh[j][1]);
                    }
            }
            BAR_ARRIVE(3 + b, NT1);

            #pragma unroll
            for (int t = 0; t < 2; t++) {
                const int nodeA = g_list[min(slot0 + t * 16 + qr, cnt - 1)];
                const int nodeB = g_list[min(slot0 + t * 16 + qr + 8, cnt - 1)];
                #pragma unroll
                for (int j = 0; j < 2; j++) {
                    const int n = nbase + j * 8 + 2 * qc;
                    const float bi0 = biass[n], bi1 = biass[n + 1];
                    float2 v0, v1;
                    v0.x = fmaxf(acc[t][j][0] + bi0, 0.f);
                    v0.y = fmaxf(acc[t][j][1] + bi1, 0.f);
                    v1.x = fmaxf(acc[t][j][2] + bi0, 0.f);
                    v1.y = fmaxf(acc[t][j][3] + bi1, 0.f);
                    *(float2*)(g_h1 + (size_t)nodeA * D + n) = v0;
                    *(float2*)(g_h1 + (size_t)nodeB * D + n) = v1;
                }
            }
        }
    }
}

// ---------------------------------------------------------------------------
// Layer 2: 32-node tile per block, grid=256, 2 blocks/SM (EXACT R11).
// ---------------------------------------------------------------------------
extern "C" __global__ void __launch_bounds__(NT2, 2)
sage_layer2(const int* __restrict__ nidx, const int* __restrict__ batch,
            float* __restrict__ out)
{
    extern __shared__ char smem[];
    const uint32_t sb = smem_u32(smem);
    float* biass = (float*)(smem + L2_BIAS);

    const int tid = threadIdx.x;
    if (tid < 64) biass[tid] = g_b2p[tid];

    for (int i = tid; i < 256 * 64; i += NT2) {
        const int k = i >> 6, n = i & 63;
        const float w = g_W2p[i];
        const float h = bfr(w);
        *(__nv_bfloat16*)(smem + L2_BHI + (n * KSTR + k) * 2) = __float2bfloat16_rn(w);
        *(__nv_bfloat16*)(smem + L2_BLO + (n * KSTR + k) * 2) = __float2bfloat16_rn(w - h);
    }

    char* Ahi = smem + L2_AHI;
    char* Alo = smem + L2_ALO;
    const int pos0 = blockIdx.x * TILE2;
    #pragma unroll
    for (int it = 0; it < 2; it++) {
        const int lin = tid + it * NT2;      // 0..1023 float4 items
        const int nn  = lin >> 5;            // node 0..31 (warp-uniform)
        const int d4  = lin & 31;
        const int bnode = __ldg(batch + pos0 + nn);
        const int4* np = (const int4*)(nidx + (size_t)bnode * S);
        const int4 na = np[0], nb4 = np[1], nc = np[2], nd = np[3];
        const int nb[16] = {na.x, na.y, na.z, na.w, nb4.x, nb4.y, nb4.z, nb4.w,
                            nc.x, nc.y, nc.z, nc.w, nd.x, nd.y, nd.z, nd.w};
        gather_split(g_h1, nb, bnode, nn, d4, Ahi, Alo);
    }
    __syncthreads();

    const int w  = tid >> 5;
    const int l  = tid & 31;
    const int qr = l >> 2, qc = l & 3;
    const int mt = w >> 3;
    const int nbase = (w & 7) * 8;

    const uint32_t aHi = sb + L2_AHI;
    const uint32_t aLo = sb + L2_ALO;

    float acc[4];
    #pragma unroll
    for (int u = 0; u < 4; u++) acc[u] = 0.f;

    #pragma unroll 4
    for (int ks = 0; ks < 16; ks++) {
        const int k0 = ks * 16;
        uint32_t ah[4], al[4];
        {
            const uint32_t r0 = (uint32_t)(mt * 16 + qr) * (KSTR * 2);
            const uint32_t r1 = r0 + 8 * (KSTR * 2);
            const uint32_t cA = (uint32_t)(k0 + 2 * qc) * 2;
            ah[0] = lds32(aHi + r0 + cA);      ah[1] = lds32(aHi + r1 + cA);
            ah[2] = lds32(aHi + r0 + cA + 16); ah[3] = lds32(aHi + r1 + cA + 16);
            al[0] = lds32(aLo + r0 + cA);      al[1] = lds32(aLo + r1 + cA);
            al[2] = lds32(aLo + r0 + cA + 16); al[3] = lds32(aLo + r1 + cA + 16);
        }
        uint32_t bh[2], bl[2];
        {
            const uint32_t nrow = (uint32_t)(nbase + qr) * (KSTR * 2);
            const uint32_t cB = (uint32_t)(k0 + 2 * qc) * 2;
            bh[0] = lds32(sb + L2_BHI + nrow + cB);
            bh[1] = lds32(sb + L2_BHI + nrow + cB + 16);
            bl[0] = lds32(sb + L2_BLO + nrow + cB);
            bl[1] = lds32(sb + L2_BLO + nrow + cB + 16);
        }
        mma_bf16(acc, ah[0], ah[1], ah[2], ah[3], bh[0], bh[1]);
        mma_bf16(acc, ah[0], ah[1], ah[2], ah[3], bl[0], bl[1]);
        mma_bf16(acc, al[0], al[1], al[2], al[3], bh[0], bh[1]);
    }

    const int r0 = pos0 + mt * 16 + qr;
    const int n = nbase + 2 * qc;
    const float bi0 = biass[n], bi1 = biass[n + 1];
    float2 v0, v1;
    v0.x = acc[0] + bi0; v0.y = acc[1] + bi1;
    v1.x = acc[2] + bi0; v1.y = acc[3] + bi1;
    *(float2*)(out + (size_t)r0 * 64 + n) = v0;
    *(float2*)(out + (size_t)(r0 + 8) * 64 + n) = v1;
}

// ---------------------------------------------------------------------------
extern "C" void kernel_launch(void* const* d_in, const int* in_sizes, int n_in,
                              void* d_out, int out_size)
{
    const float* x    = (const float*)d_in[0];
    const int*   nidx = (const int*)  d_in[1];
    const int*   batch= (const int*)  d_in[2];
    const float* W1   = (const float*)d_in[3];
    const float* b1   = (const float*)d_in[4];
    const float* W2   = (const float*)d_in[5];
    const float* b2   = (const float*)d_in[6];
    const float* Wout = (const float*)d_in[7];
    const float* bout = (const float*)d_in[8];
    float* out = (float*)d_out;

    cudaFuncSetAttribute((const void*)sage_layer1,
                         cudaFuncAttributeMaxDynamicSharedMemorySize, SMEM1_SZ);
    cudaFuncSetAttribute((const void*)sage_layer2,
                         cudaFuncAttributeMaxDynamicSharedMemorySize, SMEM2_SZ);

    void* p_mark; void* p_cnt;
    cudaGetSymbolAddress(&p_mark, g_mark);
    cudaGetSymbolAddress(&p_cnt,  g_cnt);
    cudaMemsetAsync(p_mark, 0, NNODES);
    cudaMemsetAsync(p_cnt,  0, sizeof(int));

    mark_frontier<<<NREF / 256, 256>>>(batch, nidx);
    sage_layer1<<<152, NT1, SMEM1_SZ>>>(x, nidx, W1, b1, W2, b2, Wout, bout);
    sage_layer2<<<256, NT2, SMEM2_SZ>>>(nidx, batch, out);
}